// round 12
// baseline (speedup 1.0000x reference)
#include <cuda_runtime.h>
#include <stdint.h>

#define HWC    (512*512)
#define NCH    64
#define NSEG   256
#define NB     4
#define CG     8             // channels per block
#define NCG    8             // channel groups
#define CHUNK  4096          // pixels per block = 8 image rows
#define NCHP   (HWC/CHUNK)   // 64 chunks per plane
#define TPB    256
#define NWARP  8
#define STRIP  512           // px per warp = one image row
#define TPX    64            // px per warp-tile
#define NT     (STRIP/TPX)   // 8 tiles per warp
#define TROW   68            // tile row stride u32 (68%32=4 -> uniform banks)

// Global encoded accumulator: [b][ch][s], 256KB, L2-resident.
// Zero at load; decode_kernel re-zeroes every call (graph-replay safe).
__device__ unsigned g_enc[NB * NCH * NSEG];

// Monotone float->uint encoding; enc >= 1 for any non-NaN float, 0 = identity.
__device__ __forceinline__ unsigned enc_f32(float f) {
    unsigned b = __float_as_uint(f);
    return b ^ ((unsigned)((int)b >> 31) | 0x80000000u);
}

__global__ void __launch_bounds__(TPB, 6) seg_kernel(
    const float* __restrict__ feats,   // [B, C, 512, 512]
    const int*   __restrict__ labels)  // [B, 1, 512, 512]
{
    __shared__ unsigned smax[CG * 257];            //  8.2KB, stride 257
    __shared__ unsigned tiles[NWARP * CG * TROW];  // 17.4KB, per-warp [8][68]

    const int tid  = threadIdx.x;
    const int lane = tid & 31;
    const int w    = tid >> 5;
    unsigned* tile = tiles + w * (CG * TROW);

    const int chunk = blockIdx.x;
    const int g     = blockIdx.y;
    const int b     = blockIdx.z;
    const int row   = chunk * NWARP + w;           // this warp's image row
    const int sbase = row * 512;
    const bool ybad = (row == 0) | (row == 511);

    for (int i = tid; i < CG * 257; i += TPB) smax[i] = 0u;
    __syncthreads();

    const int*   lb = labels + (size_t)b * HWC;
    const float* fb = feats + (size_t)(b * NCH + g * CG) * HWC;

    // Prefetch tile 0: lane owns px pair {2*lane, 2*lane+1}.
    float2 r2[CG];
    unsigned labp;                                 // packed labels: lo|hi<<8
    {
        const float* fp = fb + sbase + 2 * lane;
        #pragma unroll
        for (int c = 0; c < CG; ++c)
            r2[c] = *(const float2*)(fp + (size_t)c * HWC);
        int2 l2 = *(const int2*)(lb + sbase + 2 * lane);
        labp = (unsigned)l2.x | ((unsigned)l2.y << 8);
    }

    const int cs = lane & 7;                  // process-phase channel
    const int q  = lane >> 3;                 // px quarter (16 px each)
    unsigned*    rowp = smax + cs * 257;
    const uint4* trow = (const uint4*)(tile + cs * TROW + q * 16);

    for (int t = 0; t < NT; ++t) {
        // --- STS phase (lane = px pair): encode + border mask, STS.64 ---
        {
            const bool bad0 = ybad | ((t == 0) & (lane == 0));
            const bool bad1 = ybad | ((t == NT - 1) & (lane == 31));
            #pragma unroll
            for (int c = 0; c < CG; ++c) {
                uint2 e;
                e.x = bad0 ? 0u : enc_f32(r2[c].x);
                e.y = bad1 ? 0u : enc_f32(r2[c].y);
                *(uint2*)(tile + c * TROW + 2 * lane) = e;
            }
        }
        const unsigned lab_cur = labp;
        __syncwarp();

        // --- Prefetch next tile ---
        if (t + 1 < NT) {
            const float* fp = fb + sbase + (t + 1) * TPX + 2 * lane;
            #pragma unroll
            for (int c = 0; c < CG; ++c)
                r2[c] = *(const float2*)(fp + (size_t)c * HWC);
            int2 l2 = *(const int2*)(lb + sbase + (t + 1) * TPX + 2 * lane);
            labp = (unsigned)l2.x | ((unsigned)l2.y << 8);
        }

        // --- Process phase: lane = (q, cs); 16 px of own quarter ---
        #pragma unroll
        for (int k = 0; k < 4; ++k) {
            uint4 e = trow[k];
            unsigned w0 = __shfl_sync(0xffffffffu, lab_cur, 8 * q + 2 * k);
            unsigned w1 = __shfl_sync(0xffffffffu, lab_cur, 8 * q + 2 * k + 1);
            atomicMax(rowp + (w0 & 255), e.x);
            atomicMax(rowp + (w0 >> 8),  e.y);
            atomicMax(rowp + (w1 & 255), e.z);
            atomicMax(rowp + (w1 >> 8),  e.w);
        }
        __syncwarp();
    }

    __syncthreads();
    // Dump: coalesced global RED.MAX into the L2-resident table.
    unsigned* gout = g_enc + (size_t)(b * NCH + g * CG) * NSEG;
    for (int i = tid; i < CG * NSEG; i += TPB)
        atomicMax(&gout[i], smax[(i >> 8) * 257 + (i & 255)]);
}

// Decode + reset, vectorized: 1 LDG.128 + 2 STG.128 per thread.
__global__ void __launch_bounds__(TPB) decode_kernel(float* __restrict__ out) {
    const int e4 = blockIdx.x * TPB + threadIdx.x;       // 0..16383
    uint4 m = ((const uint4*)g_enc)[e4];
    ((uint4*)g_enc)[e4] = make_uint4(0u, 0u, 0u, 0u);    // reset for next call
    float4 rv;
    rv.x = (m.x == 0u) ? 0.0f : __uint_as_float((m.x & 0x80000000u) ? (m.x ^ 0x80000000u) : ~m.x);
    rv.y = (m.y == 0u) ? 0.0f : __uint_as_float((m.y & 0x80000000u) ? (m.y ^ 0x80000000u) : ~m.y);
    rv.z = (m.z == 0u) ? 0.0f : __uint_as_float((m.z & 0x80000000u) ? (m.z ^ 0x80000000u) : ~m.z);
    rv.w = (m.w == 0u) ? 0.0f : __uint_as_float((m.w & 0x80000000u) ? (m.w ^ 0x80000000u) : ~m.w);
    ((float4*)out)[e4] = rv;
}

extern "C" void kernel_launch(void* const* d_in, const int* in_sizes, int n_in,
                              void* d_out, int out_size) {
    const float* feats  = (const float*)d_in[0];
    const int*   labels = (const int*)d_in[1];
    float*       out    = (float*)d_out;

    dim3 grid(NCHP, NCG, NB);                 // (64, 8, 4) = 2048 blocks
    seg_kernel<<<grid, TPB>>>(feats, labels);

    decode_kernel<<<(NB * NCH * NSEG) / (TPB * 4), TPB>>>(out);
}

// round 13
// speedup vs baseline: 1.0765x; 1.0765x over previous
#include <cuda_runtime.h>
#include <stdint.h>

#define HWC    (512*512)
#define NCH    64
#define NSEG   256
#define NB     4
#define CG     8             // channels per block
#define NCG    8             // channel groups
#define CHUNK  4096          // pixels per block = 8 image rows
#define NCHP   (HWC/CHUNK)   // 64 chunks per plane
#define TPB    256
#define NWARP  8
#define STRIP  512           // px per warp = one image row
#define TPX    64            // px per warp-tile (lane owns a px pair)
#define NT     (STRIP/TPX)   // 8 tiles per warp

// Global encoded accumulator: [b][ch][s], 256KB, L2-resident.
// Zero at load; decode_kernel re-zeroes every call (graph-replay safe).
__device__ unsigned g_enc[NB * NCH * NSEG];
// Labels packed to u8 once per call (read 8x by seg): 1MB.
__device__ unsigned char g_lab8[NB * HWC];

// Monotone float->uint encoding; enc >= 1 for any non-NaN float, 0 = identity.
__device__ __forceinline__ unsigned enc_f32(float f) {
    unsigned b = __float_as_uint(f);
    return b ^ ((unsigned)((int)b >> 31) | 0x80000000u);
}

// Pack int32 labels (0..255) to u8: 4MB -> 1MB.
__global__ void __launch_bounds__(TPB) pack_kernel(const int* __restrict__ labels) {
    const int i = blockIdx.x * TPB + threadIdx.x;     // u32-word index
    int4 l4 = ((const int4*)labels)[i];
    ((unsigned*)g_lab8)[i] =
        (unsigned)(l4.x & 255) | ((unsigned)(l4.y & 255) << 8) |
        ((unsigned)(l4.z & 255) << 16) | ((unsigned)l4.w << 24);
}

__global__ void __launch_bounds__(TPB, 5) seg_kernel(
    const float* __restrict__ feats)   // [B, C, 512, 512]
{
    __shared__ unsigned smax[CG * 257];     // 8.2KB; row stride 257

    const int tid  = threadIdx.x;
    const int lane = tid & 31;
    const int w    = tid >> 5;

    const int chunk = blockIdx.x;
    const int g     = blockIdx.y;
    const int b     = blockIdx.z;
    const int row   = chunk * NWARP + w;    // this warp's image row
    const int sbase = row * 512;
    const bool ybad = (row == 0) | (row == 511);

    for (int i = tid; i < CG * 257; i += TPB) smax[i] = 0u;
    __syncthreads();

    const unsigned char* lbp = g_lab8 + (size_t)b * HWC + sbase;
    const float*         fb  = feats + (size_t)(b * NCH + g * CG) * HWC + sbase;

    // Prefetch tile 0: lane owns px pair {2*lane, 2*lane+1}.
    float2 cur[CG];
    unsigned short labc;
    {
        const float* fp = fb + 2 * lane;
        #pragma unroll
        for (int c = 0; c < CG; ++c)
            cur[c] = *(const float2*)(fp + (size_t)c * HWC);
        labc = *(const unsigned short*)(lbp + 2 * lane);
    }

    #pragma unroll
    for (int t = 0; t < NT; ++t) {
        // Prefetch next tile into fresh registers (unrolled -> rotation free).
        float2 nxt[CG];
        unsigned short labn = 0;
        if (t + 1 < NT) {
            const float* fp = fb + (t + 1) * TPX + 2 * lane;
            #pragma unroll
            for (int c = 0; c < CG; ++c)
                nxt[c] = *(const float2*)(fp + (size_t)c * HWC);
            labn = *(const unsigned short*)(lbp + (t + 1) * TPX + 2 * lane);
        }

        // Atomics straight from registers; border px -> enc 0 (max identity).
        {
            const bool bad0 = ybad | ((t == 0) & (lane == 0));
            const bool bad1 = ybad | ((t == NT - 1) & (lane == 31));
            const unsigned l0 = labc & 255u;
            const unsigned l1 = labc >> 8;
            #pragma unroll
            for (int c = 0; c < CG; ++c) {
                unsigned e0 = bad0 ? 0u : enc_f32(cur[c].x);
                unsigned e1 = bad1 ? 0u : enc_f32(cur[c].y);
                atomicMax(smax + c * 257 + l0, e0);
                atomicMax(smax + c * 257 + l1, e1);
            }
        }

        #pragma unroll
        for (int c = 0; c < CG; ++c) cur[c] = nxt[c];
        labc = labn;
    }

    __syncthreads();
    // Dump: coalesced global RED.MAX into the L2-resident table.
    unsigned* gout = g_enc + (size_t)(b * NCH + g * CG) * NSEG;
    for (int i = tid; i < CG * NSEG; i += TPB)
        atomicMax(&gout[i], smax[(i >> 8) * 257 + (i & 255)]);
}

// Decode + reset, vectorized: 1 LDG.128 + 2 STG.128 per thread.
__global__ void __launch_bounds__(TPB) decode_kernel(float* __restrict__ out) {
    const int e4 = blockIdx.x * TPB + threadIdx.x;       // 0..16383
    uint4 m = ((const uint4*)g_enc)[e4];
    ((uint4*)g_enc)[e4] = make_uint4(0u, 0u, 0u, 0u);    // reset for next call
    float4 rv;
    rv.x = (m.x == 0u) ? 0.0f : __uint_as_float((m.x & 0x80000000u) ? (m.x ^ 0x80000000u) : ~m.x);
    rv.y = (m.y == 0u) ? 0.0f : __uint_as_float((m.y & 0x80000000u) ? (m.y ^ 0x80000000u) : ~m.y);
    rv.z = (m.z == 0u) ? 0.0f : __uint_as_float((m.z & 0x80000000u) ? (m.z ^ 0x80000000u) : ~m.z);
    rv.w = (m.w == 0u) ? 0.0f : __uint_as_float((m.w & 0x80000000u) ? (m.w ^ 0x80000000u) : ~m.w);
    ((float4*)out)[e4] = rv;
}

extern "C" void kernel_launch(void* const* d_in, const int* in_sizes, int n_in,
                              void* d_out, int out_size) {
    const float* feats  = (const float*)d_in[0];
    const int*   labels = (const int*)d_in[1];
    float*       out    = (float*)d_out;

    pack_kernel<<<(NB * HWC / 4) / TPB, TPB>>>(labels);

    dim3 grid(NCHP, NCG, NB);                 // (64, 8, 4) = 2048 blocks
    seg_kernel<<<grid, TPB>>>(feats);

    decode_kernel<<<(NB * NCH * NSEG) / (TPB * 4), TPB>>>(out);
}